// round 1
// baseline (speedup 1.0000x reference)
#include <cuda_runtime.h>
#include <cuda_bf16.h>

#define NBOX   2048
#define RKEEP  100
#define THREADS 256
#define PER_T  (NBOX / THREADS)   // 8

// One CTA per batch row. Shared layout:
//   [0 .. 32KB)  : 4 coord arrays (l,t,r,b) — ALIASED during phase 1 by the
//                  16KB key array (keys are consumed into registers before
//                  coords are written).
//   [32KB..34KB) : suppression flags (1 byte/box)
__global__ __launch_bounds__(THREADS)
void nms_kernel(const float* __restrict__ pred, float* __restrict__ out) {
    __shared__ __align__(16) unsigned char smem_raw[NBOX * 4 * sizeof(float) + NBOX + 16];
    float* sl = (float*)smem_raw;
    float* st = sl + NBOX;
    float* sr = st + NBOX;
    float* sb = sr + NBOX;
    unsigned char* supp = (unsigned char*)(sb + NBOX);
    unsigned long long* skey = (unsigned long long*)smem_raw;  // aliases sl/st (phase 1 only)
    __shared__ int sh_i;

    const int b   = blockIdx.x;
    const int tid = threadIdx.x;
    const float* p = pred + (size_t)b * NBOX * 5;

    // ---- Phase 1: stable descending sort keys -------------------------------
    // key = (score_bits << 32) | (N-1-i). Scores are non-negative f32, so the
    // bit pattern is order-preserving. Descending sort on the composite gives
    // descending score with ascending original index on ties == stable
    // jnp.argsort(-scores).
    for (int i = tid; i < NBOX; i += THREADS) {
        unsigned int sbits = __float_as_uint(p[i * 5 + 0]);
        skey[i] = ((unsigned long long)sbits << 32) | (unsigned)(NBOX - 1 - i);
    }
    __syncthreads();

    // Bitonic sort, descending, 2048 keys, 66 stages.
    for (int k = 2; k <= NBOX; k <<= 1) {
        for (int j = k >> 1; j > 0; j >>= 1) {
            #pragma unroll
            for (int u = 0; u < PER_T; u++) {
                int idx = tid + u * THREADS;
                int ixj = idx ^ j;
                if (ixj > idx) {
                    unsigned long long a = skey[idx], c = skey[ixj];
                    bool desc = ((idx & k) == 0);
                    if (desc ? (a < c) : (a > c)) { skey[idx] = c; skey[ixj] = a; }
                }
            }
            __syncthreads();
        }
    }

    // ---- Phase 2: gather coords through registers (keys buffer is reused) ---
    float rl[PER_T], rt[PER_T], rr[PER_T], rb[PER_T];
    #pragma unroll
    for (int u = 0; u < PER_T; u++) {
        int i = tid + u * THREADS;
        int orig = NBOX - 1 - (int)(skey[i] & 0xFFFFFFFFu);
        const float* q = p + (size_t)orig * 5;
        rl[u] = q[1]; rt[u] = q[2]; rr[u] = q[3]; rb[u] = q[4];
    }
    __syncthreads();   // all keys consumed before coords overwrite them
    #pragma unroll
    for (int u = 0; u < PER_T; u++) {
        int i = tid + u * THREADS;
        sl[i] = rl[u]; st[i] = rt[u]; sr[i] = rr[u]; sb[i] = rb[u];
        supp[i] = 0;
    }
    __syncthreads();

    // ---- Phase 3: greedy NMS, early-exit at RKEEP kept ----------------------
    float* ob = out + (size_t)b * RKEEP * 3;
    int slot = 0;
    int cur  = 0;   // meaningful on thread 0 only
    while (true) {
        if (tid == 0) {
            int i = cur;
            while (i < NBOX && supp[i]) i++;
            sh_i = i;
            cur  = i + 1;
        }
        __syncthreads();
        const int i = sh_i;
        if (i >= NBOX) break;

        const float li = sl[i], ti = st[i], ri = sr[i], bi = sb[i];
        if (tid == 0) {
            ob[slot * 3 + 0] = ti;   // vals = p[:, 2:] = (top, right, bottom)
            ob[slot * 3 + 1] = ri;
            ob[slot * 3 + 2] = bi;
        }
        slot++;
        if (slot == RKEEP) break;

        // Suppress tail: overlap[i][j] = inter / area[j] >= 0.5 -> drop j.
        for (int jj = i + 1 + tid; jj < NBOX; jj += THREADS) {
            if (!supp[jj]) {
                float il = fmaxf(li, sl[jj]);
                float it = fmaxf(ti, st[jj]);
                float ir = fminf(ri, sr[jj]);
                float ib = fminf(bi, sb[jj]);
                float inter = fmaxf(0.f, ir - il) * fmaxf(0.f, ib - it);
                float area  = (sr[jj] - sl[jj]) * (sb[jj] - st[jj]);
                // IEEE-rounded divide: decision bit matches the JAX reference
                // regardless of the harness's fast-math flags.
                if (__fdiv_rn(inter, area) >= 0.5f) supp[jj] = 1;
            }
        }
        __syncthreads();
    }

    // Zero-fill unused slots (out is poisoned to 0xAA by the harness).
    for (int k2 = slot * 3 + tid; k2 < RKEEP * 3; k2 += THREADS) ob[k2] = 0.f;
}

extern "C" void kernel_launch(void* const* d_in, const int* in_sizes, int n_in,
                              void* d_out, int out_size) {
    const float* pred = (const float*)d_in[0];   // [32, 2048, 5] f32
    float* out = (float*)d_out;                  // [32, 100, 3] f32
    (void)in_sizes; (void)n_in; (void)out_size;
    nms_kernel<<<32, THREADS>>>(pred, out);
}

// round 5
// speedup vs baseline: 5.2912x; 5.2912x over previous
#include <cuda_runtime.h>
#include <cuda_bf16.h>

#define NBOX    2048
#define RKEEP   100
#define THREADS 512
#define PER_T   (NBOX / THREADS)     // 4 boxes owned per thread
#define NPAIR   (NBOX / 2)           // 1024 compare-exchange pairs per stage
#define PAIRS_T (NPAIR / THREADS)    // 2 pairs per thread

// One CTA per batch row.
// Smem: sbox (float4 l,t,r,b) 32KB — front 16KB aliased by 64-bit sort keys,
//       sthr 8KB (exact suppression threshold per box), supp 2KB. Total 42KB.
__global__ __launch_bounds__(THREADS)
void nms_kernel(const float* __restrict__ pred, float* __restrict__ out) {
    __shared__ __align__(16) float4 sbox[NBOX];
    __shared__ float sthr[NBOX];
    __shared__ unsigned char supp[NBOX];
    unsigned long long* skey = (unsigned long long*)sbox;  // phase-1 alias

    const int b   = blockIdx.x;
    const int tid = threadIdx.x;
    const float* p = pred + (size_t)b * NBOX * 5;

    // ---- Phase 1: stable descending sort of (score, index) ------------------
    // key = (score_bits<<32) | (N-1-i): scores >= 0 so bits are order-preserving;
    // descending composite == stable jnp.argsort(-scores).
    for (int i = tid; i < NBOX; i += THREADS) {
        unsigned sbits = __float_as_uint(p[i * 5 + 0]);
        skey[i] = ((unsigned long long)sbits << 32) | (unsigned)(NBOX - 1 - i);
    }
    __syncthreads();

    // Branchless pair-based bitonic sort (descending).
    // Substage body: 2 pairs/thread, unconditional SELs (no divergent branch).
    auto substage = [&](int k, int j) {
        #pragma unroll
        for (int u = 0; u < PAIRS_T; u++) {
            int pr  = tid + u * THREADS;
            int idx = ((pr & ~(j - 1)) << 1) | (pr & (j - 1));
            int ixj = idx | j;
            unsigned long long a = skey[idx], c = skey[ixj];
            unsigned long long hi = (a > c) ? a : c;
            unsigned long long lo = (a > c) ? c : a;
            bool desc = ((idx & k) == 0);
            skey[idx] = desc ? hi : lo;
            skey[ixj] = desc ? lo : hi;
        }
    };

    for (int k = 2; k <= NBOX; k <<= 1) {
        int j = k >> 1;
        // Cross-warp substages (element blocks span warps): full barrier.
        for (; j >= 64; j >>= 1) {
            substage(k, j);
            __syncthreads();
        }
        // Warp-local substages: for j <= 32, a 32-aligned pair block maps to a
        // 64-aligned element block owned exclusively by one warp (both idx and
        // idx|j stay inside). __syncwarp orders intra-warp smem accesses.
        for (; j > 0; j >>= 1) {
            substage(k, j);
            __syncwarp();
        }
        __syncthreads();   // publish warp-local results before next k stage
    }

    // ---- Phase 2: gather coords into registers, build smem tables -----------
    // Thread t owns boxes {t, t+512, t+1024, t+1536} for the whole greedy phase.
    float4 mybox[PER_T];
    float  mythr[PER_T];
    #pragma unroll
    for (int u = 0; u < PER_T; u++) {
        int i = tid + u * THREADS;
        int orig = NBOX - 1 - (int)(skey[i] & 0xFFFFFFFFu);
        const float* q = p + (size_t)orig * 5;
        float l = q[1], t = q[2], r = q[3], bo = q[4];
        mybox[u] = make_float4(l, t, r, bo);
        float area = (r - l) * (bo - t);             // same rounding as reference
        // Exact threshold: RN(inter/area) >= 0.5  <=>  inter >= RU(area*m),
        // m = 0.5 - 2^-26 (midpoint below 0.5; tie rounds-to-even up to 0.5).
        double dm = (double)area * (0.5 - 1.4901161193847656e-8 /* 2^-26 */);
        mythr[u] = __double2float_ru(dm);
    }
    __syncthreads();   // all key reads done before coords overwrite the alias
    #pragma unroll
    for (int u = 0; u < PER_T; u++) {
        int i = tid + u * THREADS;
        sbox[i] = mybox[u];
        sthr[i] = mythr[u];
        supp[i] = 0;
    }
    __syncthreads();

    // ---- Phase 3: greedy NMS, 1 barrier per kept box, early exit at RKEEP ---
    float* ob = out + (size_t)b * RKEEP * 3;
    int cur = 0, slot = 0;
    while (true) {
        // All threads redundantly find the next unsuppressed box (uniform,
        // broadcast smem reads; typically advances one step).
        while (cur < NBOX && supp[cur]) cur++;
        int i = cur++;
        if (i >= NBOX) break;

        float4 bi = sbox[i];                  // broadcast LDS.128
        if (tid == 0) {                       // vals = (top, right, bottom)
            ob[slot * 3 + 0] = bi.y;
            ob[slot * 3 + 1] = bi.z;
            ob[slot * 3 + 2] = bi.w;
        }
        slot++;
        if (slot == RKEEP) break;

        // Branchless suppression over this thread's owned boxes. Evaluating
        // boxes jj <= i (incl. i itself) is harmless: those supp bytes are
        // never read again (find-next scans only from cur > i).
        #pragma unroll
        for (int u = 0; u < PER_T; u++) {
            float il = fmaxf(bi.x, mybox[u].x);
            float it = fmaxf(bi.y, mybox[u].y);
            float ir = fminf(bi.z, mybox[u].z);
            float ib = fminf(bi.w, mybox[u].w);
            float inter = fmaxf(0.f, ir - il) * fmaxf(0.f, ib - it);
            if (inter >= mythr[u]) supp[tid + u * THREADS] = 1;   // @P STS
        }
        __syncthreads();
    }

    // Zero-fill unused output slots (out is poisoned by the harness).
    for (int k2 = slot * 3 + tid; k2 < RKEEP * 3; k2 += THREADS) ob[k2] = 0.f;
}

extern "C" void kernel_launch(void* const* d_in, const int* in_sizes, int n_in,
                              void* d_out, int out_size) {
    const float* pred = (const float*)d_in[0];   // [32, 2048, 5] f32
    float* out = (float*)d_out;                  // [32, 100, 3] f32
    (void)in_sizes; (void)n_in; (void)out_size;
    nms_kernel<<<32, THREADS>>>(pred, out);
}

// round 6
// speedup vs baseline: 7.0486x; 1.3321x over previous
#include <cuda_runtime.h>
#include <cuda_bf16.h>

#define NBOX    2048
#define RKEEP   100
#define THREADS 512
#define WIN     THREADS              // greedy window = 512 boxes, 1 per thread
#define NWIN    (NBOX / WIN)         // 4
#define NPAIR   (NBOX / 2)
#define PAIRS_T (NPAIR / THREADS)    // 2

// One CTA per batch row. Smem ~26.2KB: persistent sorted keys, per-window box
// cache, kept-box list (for exact window-extension replay), per-window supp.
__global__ __launch_bounds__(THREADS)
void nms_kernel(const float* __restrict__ pred, float* __restrict__ out) {
    __shared__ unsigned long long skey[NBOX];       // 16KB (persists all phases)
    __shared__ __align__(16) float4 wbox[WIN];      // 8KB  window boxes (l,t,r,b)
    __shared__ __align__(16) float4 klist[RKEEP];   // kept boxes, for replay
    __shared__ unsigned char supp[WIN];             // window suppression flags

    const int b   = blockIdx.x;
    const int tid = threadIdx.x;
    const float* p = pred + (size_t)b * NBOX * 5;

    // ---- Phase 1: stable descending sort keys -------------------------------
    // key = (score_bits<<32) | (N-1-i). Scores >= 0 -> bits order-preserving;
    // descending composite == stable jnp.argsort(-scores).
    for (int i = tid; i < NBOX; i += THREADS) {
        unsigned sbits = __float_as_uint(p[i * 5 + 0]);
        skey[i] = ((unsigned long long)sbits << 32) | (unsigned)(NBOX - 1 - i);
    }
    __syncthreads();

    // Branchless pair-based bitonic sort (descending), unconditional SELs.
    auto substage = [&](int k, int j) {
        #pragma unroll
        for (int u = 0; u < PAIRS_T; u++) {
            int pr  = tid + u * THREADS;
            int idx = ((pr & ~(j - 1)) << 1) | (pr & (j - 1));
            int ixj = idx | j;
            unsigned long long a = skey[idx], c = skey[ixj];
            unsigned long long hi = (a > c) ? a : c;
            unsigned long long lo = (a > c) ? c : a;
            bool desc = ((idx & k) == 0);
            skey[idx] = desc ? hi : lo;
            skey[ixj] = desc ? lo : hi;
        }
    };

    for (int k = 2; k <= NBOX; k <<= 1) {
        int j = k >> 1;
        // Cross-warp substages: full barrier.
        for (; j >= 64; j >>= 1) {
            substage(k, j);
            __syncthreads();
        }
        // j <= 32: 32-aligned pair blocks map to warp-exclusive 64-aligned
        // element blocks (both idx and idx|j stay inside) -> warp sync only.
        for (; j > 0; j >>= 1) {
            substage(k, j);
            __syncwarp();
        }
        __syncthreads();
    }

    // ---- Phase 2+3: windowed greedy NMS, exact, early-exit at RKEEP ---------
    // Only sorted indices < cur_final (~130) are ever examined as candidates;
    // window 0 (512 boxes) almost always suffices. Fallback windows replay the
    // kept list first, preserving bit-exact greedy semantics.
    float* ob = out + (size_t)b * RKEEP * 3;
    int slot = 0;
    for (int w = 0; w < NWIN && slot < RKEEP; w++) {
        // Gather my box (1 per thread) straight into registers.
        int gi   = w * WIN + tid;
        int orig = NBOX - 1 - (int)(skey[gi] & 0xFFFFFFFFu);
        const float* q = p + (size_t)orig * 5;
        float l = q[1], t = q[2], r = q[3], bo = q[4];
        float4 mb = make_float4(l, t, bo == bo ? r : r, bo);  // keep simple
        mb = make_float4(l, t, r, bo);
        float area = (r - l) * (bo - t);            // reference rounding
        // Exact: RN(inter/area) >= 0.5  <=>  inter >= RU(area*(0.5 - 2^-26)).
        // (double product exact at <=51 mantissa bits; midpoint tie rounds-to-
        // even up to 0.5, i.e. onto the suppress side.)
        float thr = __double2float_ru((double)area *
                                      (0.5 - 1.4901161193847656e-8));

        // Replay previously kept boxes onto this window (no-op for window 0).
        unsigned char s = 0;
        for (int k2 = 0; k2 < slot; k2++) {
            float4 bi = klist[k2];
            float il = fmaxf(bi.x, mb.x), it = fmaxf(bi.y, mb.y);
            float ir = fminf(bi.z, mb.z), ib = fminf(bi.w, mb.w);
            float inter = fmaxf(0.f, ir - il) * fmaxf(0.f, ib - it);
            if (inter >= thr) s = 1;
        }
        wbox[tid] = mb;
        supp[tid] = s;
        __syncthreads();

        int cur = 0;
        while (true) {
            // Uniform redundant scan for next alive candidate (broadcast LDS).
            while (cur < WIN && supp[cur]) cur++;
            if (cur >= WIN) break;               // window exhausted -> extend
            int i = cur++;

            float4 bi = wbox[i];                 // broadcast LDS.128
            if (tid == i) {                      // owner emits output + klist
                ob[slot * 3 + 0] = mb.y;         // vals = (top, right, bottom)
                ob[slot * 3 + 1] = mb.z;
                ob[slot * 3 + 2] = mb.w;
                klist[slot] = mb;
            }
            slot++;
            if (slot == RKEEP) break;

            // One IoU per thread, branchless; predicated STS on suppression.
            float il = fmaxf(bi.x, mb.x), it = fmaxf(bi.y, mb.y);
            float ir = fminf(bi.z, mb.z), ib = fminf(bi.w, mb.w);
            float inter = fmaxf(0.f, ir - il) * fmaxf(0.f, ib - it);
            if (inter >= thr) supp[tid] = 1;
            __syncthreads();
        }
        __syncthreads();   // order supp/wbox/klist across window boundary
    }

    // Zero-fill unused output slots (out is poisoned by the harness).
    for (int k2 = slot * 3 + tid; k2 < RKEEP * 3; k2 += THREADS) ob[k2] = 0.f;
}

extern "C" void kernel_launch(void* const* d_in, const int* in_sizes, int n_in,
                              void* d_out, int out_size) {
    const float* pred = (const float*)d_in[0];   // [32, 2048, 5] f32
    float* out = (float*)d_out;                  // [32, 100, 3] f32
    (void)in_sizes; (void)n_in; (void)out_size;
    nms_kernel<<<32, THREADS>>>(pred, out);
}